// round 1
// baseline (speedup 1.0000x reference)
#include <cuda_runtime.h>
#include <cuda_bf16.h>

// TriplePairwiseCEFocalLoss — B=8192 rows, S=4096 cols.
// per_sample[b] = mean over negatives j of (1-pt)^2 * softplus(scores[b,j]-pos)
//   where pos = scores[b, tail[b]], pt = clip(sigmoid(pos - scores[b,j]), 1e-7, 1-1e-7)
//   negatives: mask[b,j]==1 AND j != head[b] AND j != tail[b]
// output = sum_b per_sample[b] / B
//
// Strategy: warp-per-row, float4/int4 vector loads (HBM-bound, ~256MiB traffic),
// 3 MUFU (EX2, LG2, RCP) per element — stays under the HBM roofline.
// Deterministic 2-kernel reduction (no float atomics).

#define BB 8192
#define SS 4096
#define S4 (SS / 4)          // 1024 float4 per row
#define THREADS 256
#define WARPS_PER_CTA (THREADS / 32)

__device__ float g_per_sample[BB];

__device__ __forceinline__ void accum_elem(float sc, float pos, bool neg,
                                           float& fs, float& cs) {
    float x  = sc - pos;
    float ex = __expf(x);          // EX2
    float w  = ex + 1.0f;
    float sp = __logf(w);          // LG2  == softplus(x) == -logpt
    float pt;
    asm("rcp.approx.f32 %0, %1;" : "=f"(pt) : "f"(w));   // RCP: pt = 1/(1+e^x)
    pt = fminf(fmaxf(pt, 1e-7f), 1.0f - 1e-7f);
    float om = 1.0f - pt;
    float fl = om * om * sp;       // focal loss (ALPHA=1, GAMMA=2)
    if (neg) { fs += fl; cs += 1.0f; }
}

__global__ __launch_bounds__(THREADS, 8)
void focal_row_kernel(const float* __restrict__ scores,
                      const int*   __restrict__ head_position,
                      const int*   __restrict__ tail_position,
                      const int*   __restrict__ score_mask) {
    int warp_global = (blockIdx.x * WARPS_PER_CTA) + (threadIdx.x >> 5);
    int lane = threadIdx.x & 31;
    if (warp_global >= BB) return;

    const float* __restrict__ srow = scores     + (size_t)warp_global * SS;
    const int*   __restrict__ mrow = score_mask + (size_t)warp_global * SS;
    const int h = __ldg(head_position + warp_global);
    const int t = __ldg(tail_position + warp_global);
    const float pos = __ldg(srow + t);    // broadcast load (all lanes same addr)

    float fs = 0.0f, cs = 0.0f;

    const float4* __restrict__ s4 = (const float4*)srow;
    const int4*   __restrict__ m4 = (const int4*)mrow;

    // 32 iterations per lane; unroll for MLP.
    #pragma unroll 4
    for (int i = lane; i < S4; i += 32) {
        float4 sc = __ldg(s4 + i);
        int4   mk = __ldg(m4 + i);
        int jb = i * 4;
        bool n0 = (mk.x == 1) && (jb + 0 != h) && (jb + 0 != t);
        bool n1 = (mk.y == 1) && (jb + 1 != h) && (jb + 1 != t);
        bool n2 = (mk.z == 1) && (jb + 2 != h) && (jb + 2 != t);
        bool n3 = (mk.w == 1) && (jb + 3 != h) && (jb + 3 != t);
        accum_elem(sc.x, pos, n0, fs, cs);
        accum_elem(sc.y, pos, n1, fs, cs);
        accum_elem(sc.z, pos, n2, fs, cs);
        accum_elem(sc.w, pos, n3, fs, cs);
    }

    // warp tree-reduce (shfl only)
    #pragma unroll
    for (int off = 16; off > 0; off >>= 1) {
        fs += __shfl_xor_sync(0xffffffffu, fs, off);
        cs += __shfl_xor_sync(0xffffffffu, cs, off);
    }

    if (lane == 0) {
        float per = (cs > 0.5f) ? (fs / cs) : 0.0f;
        g_per_sample[warp_global] = per;
    }
}

__global__ void reduce_kernel(float* __restrict__ out) {
    __shared__ float sh[1024];
    float s = 0.0f;
    for (int i = threadIdx.x; i < BB; i += 1024)
        s += g_per_sample[i];
    sh[threadIdx.x] = s;
    __syncthreads();
    #pragma unroll
    for (int k = 512; k > 0; k >>= 1) {
        if (threadIdx.x < (unsigned)k) sh[threadIdx.x] += sh[threadIdx.x + k];
        __syncthreads();
    }
    if (threadIdx.x == 0) out[0] = sh[0] * (1.0f / (float)BB);
}

extern "C" void kernel_launch(void* const* d_in, const int* in_sizes, int n_in,
                              void* d_out, int out_size) {
    const float* scores = (const float*)d_in[0];
    const int*   head   = (const int*)d_in[1];
    const int*   tail   = (const int*)d_in[2];
    const int*   mask   = (const int*)d_in[3];
    float* out = (float*)d_out;

    dim3 grid(BB / WARPS_PER_CTA);   // 1024 CTAs
    focal_row_kernel<<<grid, THREADS>>>(scores, head, tail, mask);
    reduce_kernel<<<1, 1024>>>(out);
}